// round 1
// baseline (speedup 1.0000x reference)
#include <cuda_runtime.h>
#include <cstdint>

// Problem constants
#define TT 2048           // sequence length T
#define NN 4096           // head feature dim N
#define NHT 8             // B * N_HEAD = 2*4 combined head-batch
#define TILE 128
#define BK 16
#define PADB 132          // 128 + 4 pad: keeps 16B alignment of rows, kills STS conflicts

// Scratch (static device globals — allocation-free per harness rules)
__device__ float g_QR[(size_t)NHT * TT * NN];   // 256 MB: rotated Q
__device__ float g_S[(size_t)NHT * TT * TT];    // 128 MB: scores

// ---------------------------------------------------------------------------
// Kernel 1: RoPE.  QR = Q*cos(ph) + rot(Q)*sin(ph)
// freq[n] = 2^(-floor(n/2)*2/256) / (2*pi);  ph = frac(t*freq)*2*pi
// Pairs (2i, 2i+1) share a frequency: out_even = e*c - o*s ; out_odd = o*c + e*s
// ---------------------------------------------------------------------------
__global__ void rope_kernel(const float* __restrict__ Q) {
    size_t pair = (size_t)blockIdx.x * blockDim.x + threadIdx.x;
    // total pairs = NHT*TT*NN/2 = 33554432
    int n2 = (int)(pair % (NN / 2));
    size_t row = pair / (NN / 2);
    int t = (int)(row % TT);

    const float inv2pi = 0.15915494309189535f; // 1/(2*pi)
    float freq = exp2f(-(float)(n2 * 2) * (1.0f / 256.0f)) * inv2pi;
    float phase = (float)t * freq;
    float frac = phase - floorf(phase);
    float s, c;
    sincospif(2.0f * frac, &s, &c);

    float2 v = ((const float2*)Q)[pair];
    float2 o;
    o.x = v.x * c - v.y * s;
    o.y = v.y * c + v.x * s;
    ((float2*)g_QR)[pair] = o;
}

// ---------------------------------------------------------------------------
// Kernel 2: S = scale * QR @ QR^T   (NT gemm, per head; M=N=2048, K=4096)
// 128x128 tile, BK=16, 256 threads, 8x8 per-thread accum.
// ---------------------------------------------------------------------------
__global__ __launch_bounds__(256, 2)
void gemm1_nt_kernel() {
    const int h = blockIdx.z;
    const float* __restrict__ Ah = g_QR + (size_t)h * TT * NN;
    float* __restrict__ Ch = g_S + (size_t)h * TT * TT;
    const int row0 = blockIdx.y * TILE;
    const int col0 = blockIdx.x * TILE;

    __shared__ float As[BK][PADB];
    __shared__ float Bs[BK][PADB];

    const int tid = threadIdx.x;
    const int tx = tid & 15;
    const int ty = tid >> 4;
    const int lrow = tid >> 2;        // 0..63 (also row lrow+64)
    const int lc = (tid & 3) * 4;     // 0,4,8,12

    const float4* Ar0 = (const float4*)(Ah + (size_t)(row0 + lrow) * NN + lc);
    const float4* Ar1 = (const float4*)(Ah + (size_t)(row0 + lrow + 64) * NN + lc);
    const float4* Br0 = (const float4*)(Ah + (size_t)(col0 + lrow) * NN + lc);
    const float4* Br1 = (const float4*)(Ah + (size_t)(col0 + lrow + 64) * NN + lc);

    float acc[8][8];
#pragma unroll
    for (int i = 0; i < 8; i++)
#pragma unroll
        for (int j = 0; j < 8; j++) acc[i][j] = 0.0f;

    for (int k0 = 0; k0 < NN; k0 += BK) {
        float4 a0 = Ar0[k0 >> 2];
        float4 a1 = Ar1[k0 >> 2];
        float4 b0 = Br0[k0 >> 2];
        float4 b1 = Br1[k0 >> 2];
        __syncthreads();
        As[lc + 0][lrow] = a0.x; As[lc + 1][lrow] = a0.y;
        As[lc + 2][lrow] = a0.z; As[lc + 3][lrow] = a0.w;
        As[lc + 0][lrow + 64] = a1.x; As[lc + 1][lrow + 64] = a1.y;
        As[lc + 2][lrow + 64] = a1.z; As[lc + 3][lrow + 64] = a1.w;
        Bs[lc + 0][lrow] = b0.x; Bs[lc + 1][lrow] = b0.y;
        Bs[lc + 2][lrow] = b0.z; Bs[lc + 3][lrow] = b0.w;
        Bs[lc + 0][lrow + 64] = b1.x; Bs[lc + 1][lrow + 64] = b1.y;
        Bs[lc + 2][lrow + 64] = b1.z; Bs[lc + 3][lrow + 64] = b1.w;
        __syncthreads();
#pragma unroll
        for (int kk = 0; kk < BK; kk++) {
            float4 ta0 = *(const float4*)&As[kk][ty * 4];
            float4 ta1 = *(const float4*)&As[kk][64 + ty * 4];
            float4 tb0 = *(const float4*)&Bs[kk][tx * 4];
            float4 tb1 = *(const float4*)&Bs[kk][64 + tx * 4];
            float ra[8] = {ta0.x, ta0.y, ta0.z, ta0.w, ta1.x, ta1.y, ta1.z, ta1.w};
            float rb[8] = {tb0.x, tb0.y, tb0.z, tb0.w, tb1.x, tb1.y, tb1.z, tb1.w};
#pragma unroll
            for (int i = 0; i < 8; i++)
#pragma unroll
                for (int j = 0; j < 8; j++) acc[i][j] += ra[i] * rb[j];
        }
    }

    const float scale = 1.0f / 64.0f;   // 1/sqrt(4096)
#pragma unroll
    for (int i = 0; i < 8; i++) {
        int r = row0 + ((i < 4) ? (ty * 4 + i) : (64 + ty * 4 + i - 4));
        float4 o0 = make_float4(acc[i][0] * scale, acc[i][1] * scale,
                                acc[i][2] * scale, acc[i][3] * scale);
        float4 o1 = make_float4(acc[i][4] * scale, acc[i][5] * scale,
                                acc[i][6] * scale, acc[i][7] * scale);
        *(float4*)&Ch[(size_t)r * TT + col0 + tx * 4] = o0;
        *(float4*)&Ch[(size_t)r * TT + col0 + 64 + tx * 4] = o1;
    }
}

// ---------------------------------------------------------------------------
// Kernel 3: O = S @ V   (NN gemm, per head; M=2048, N=4096, K=2048)
// ---------------------------------------------------------------------------
__global__ __launch_bounds__(256, 2)
void gemm2_nn_kernel(const float* __restrict__ V, float* __restrict__ O) {
    const int h = blockIdx.z;
    const float* __restrict__ Sh = g_S + (size_t)h * TT * TT;
    const float* __restrict__ Vh = V + (size_t)h * TT * NN;
    float* __restrict__ Oh = O + (size_t)h * TT * NN;
    const int row0 = blockIdx.y * TILE;
    const int col0 = blockIdx.x * TILE;

    __shared__ float As[BK][PADB];
    __shared__ float Bs[BK][PADB];

    const int tid = threadIdx.x;
    const int tx = tid & 15;
    const int ty = tid >> 4;
    const int lrow = tid >> 2;        // A-tile: rows lrow, lrow+64; cols lc..lc+3
    const int lc = (tid & 3) * 4;
    const int bkr = tid >> 5;         // B-tile: rows bkr, bkr+8
    const int bc = (tid & 31) * 4;    // cols bc..bc+3

    float acc[8][8];
#pragma unroll
    for (int i = 0; i < 8; i++)
#pragma unroll
        for (int j = 0; j < 8; j++) acc[i][j] = 0.0f;

    for (int k0 = 0; k0 < TT; k0 += BK) {
        float4 a0 = *(const float4*)&Sh[(size_t)(row0 + lrow) * TT + k0 + lc];
        float4 a1 = *(const float4*)&Sh[(size_t)(row0 + lrow + 64) * TT + k0 + lc];
        float4 b0 = *(const float4*)&Vh[(size_t)(k0 + bkr) * NN + col0 + bc];
        float4 b1 = *(const float4*)&Vh[(size_t)(k0 + bkr + 8) * NN + col0 + bc];
        __syncthreads();
        As[lc + 0][lrow] = a0.x; As[lc + 1][lrow] = a0.y;
        As[lc + 2][lrow] = a0.z; As[lc + 3][lrow] = a0.w;
        As[lc + 0][lrow + 64] = a1.x; As[lc + 1][lrow + 64] = a1.y;
        As[lc + 2][lrow + 64] = a1.z; As[lc + 3][lrow + 64] = a1.w;
        *(float4*)&Bs[bkr][bc] = b0;
        *(float4*)&Bs[bkr + 8][bc] = b1;
        __syncthreads();
#pragma unroll
        for (int kk = 0; kk < BK; kk++) {
            float4 ta0 = *(const float4*)&As[kk][ty * 4];
            float4 ta1 = *(const float4*)&As[kk][64 + ty * 4];
            float4 tb0 = *(const float4*)&Bs[kk][tx * 4];
            float4 tb1 = *(const float4*)&Bs[kk][64 + tx * 4];
            float ra[8] = {ta0.x, ta0.y, ta0.z, ta0.w, ta1.x, ta1.y, ta1.z, ta1.w};
            float rb[8] = {tb0.x, tb0.y, tb0.z, tb0.w, tb1.x, tb1.y, tb1.z, tb1.w};
#pragma unroll
            for (int i = 0; i < 8; i++)
#pragma unroll
                for (int j = 0; j < 8; j++) acc[i][j] += ra[i] * rb[j];
        }
    }

#pragma unroll
    for (int i = 0; i < 8; i++) {
        int r = row0 + ((i < 4) ? (ty * 4 + i) : (64 + ty * 4 + i - 4));
        float4 o0 = make_float4(acc[i][0], acc[i][1], acc[i][2], acc[i][3]);
        float4 o1 = make_float4(acc[i][4], acc[i][5], acc[i][6], acc[i][7]);
        *(float4*)&Oh[(size_t)r * NN + col0 + tx * 4] = o0;
        *(float4*)&Oh[(size_t)r * NN + col0 + 64 + tx * 4] = o1;
    }
}

// ---------------------------------------------------------------------------
// Launch.  Inputs (metadata order): Q, K (unused by reference!), V.
// Output: fp32 [2,4,2048,4096].
// ---------------------------------------------------------------------------
extern "C" void kernel_launch(void* const* d_in, const int* in_sizes, int n_in,
                              void* d_out, int out_size) {
    const float* Q = (const float*)d_in[0];
    const float* V = (const float*)d_in[2];
    float* O = (float*)d_out;

    // 1) RoPE: 33,554,432 pairs
    {
        int threads = 256;
        int blocks = (int)(((size_t)NHT * TT * NN / 2) / threads);
        rope_kernel<<<blocks, threads>>>(Q);
    }
    // 2) S = scale * QR @ QR^T
    {
        dim3 grid(TT / TILE, TT / TILE, NHT);  // 16 x 16 x 8
        gemm1_nt_kernel<<<grid, 256>>>();
    }
    // 3) O = S @ V
    {
        dim3 grid(NN / TILE, TT / TILE, NHT);  // 32 x 16 x 8
        gemm2_nn_kernel<<<grid, 256>>>(V, O);
    }
}

// round 3
// speedup vs baseline: 2.6666x; 2.6666x over previous
#include <cuda_runtime.h>
#include <cuda_bf16.h>
#include <cstdint>

#define TT 2048
#define NN 4096
#define NHT 8
#define AP 40          // smem pitch for 32-wide bf16 tiles (80B rows -> conflict-free LDSM)
#define BPITCH 136     // smem pitch for 128-wide bf16 tiles (272B rows -> conflict-free LDSM.T)

// Scratch: bf16 hi/lo splits (allocation-free device globals)
__device__ __align__(128) __nv_bfloat16 g_QRh[(size_t)NHT * TT * NN];
__device__ __align__(128) __nv_bfloat16 g_QRl[(size_t)NHT * TT * NN];
__device__ __align__(128) __nv_bfloat16 g_Vh[(size_t)NHT * TT * NN];
__device__ __align__(128) __nv_bfloat16 g_Vl[(size_t)NHT * TT * NN];
__device__ __align__(128) __nv_bfloat16 g_Sh[(size_t)NHT * TT * TT];
__device__ __align__(128) __nv_bfloat16 g_Sl[(size_t)NHT * TT * TT];

__device__ __forceinline__ uint32_t smaddr(const void* p) {
    return (uint32_t)__cvta_generic_to_shared(p);
}
__device__ __forceinline__ void ldsm4(uint32_t* r, uint32_t a) {
    asm volatile("ldmatrix.sync.aligned.m8n8.x4.shared.b16 {%0,%1,%2,%3},[%4];"
                 : "=r"(r[0]), "=r"(r[1]), "=r"(r[2]), "=r"(r[3]) : "r"(a));
}
__device__ __forceinline__ void ldsm4t(uint32_t* r, uint32_t a) {
    asm volatile("ldmatrix.sync.aligned.m8n8.x4.trans.shared.b16 {%0,%1,%2,%3},[%4];"
                 : "=r"(r[0]), "=r"(r[1]), "=r"(r[2]), "=r"(r[3]) : "r"(a));
}
__device__ __forceinline__ void mma16816(float* d, const uint32_t* a, const uint32_t* b) {
    asm volatile("mma.sync.aligned.m16n8k16.row.col.f32.bf16.bf16.f32 "
                 "{%0,%1,%2,%3},{%4,%5,%6,%7},{%8,%9},{%0,%1,%2,%3};"
                 : "+f"(d[0]), "+f"(d[1]), "+f"(d[2]), "+f"(d[3])
                 : "r"(a[0]), "r"(a[1]), "r"(a[2]), "r"(a[3]), "r"(b[0]), "r"(b[1]));
}
__device__ __forceinline__ void split2(float x, __nv_bfloat16& h, __nv_bfloat16& l) {
    h = __float2bfloat16(x);
    l = __float2bfloat16(x - __bfloat162float(h));
}

// ---------------------------------------------------------------------------
// Kernel 1: RoPE + hi/lo bf16 split of QR
// ---------------------------------------------------------------------------
__global__ void rope_split(const float* __restrict__ Q) {
    size_t pair = (size_t)blockIdx.x * blockDim.x + threadIdx.x;
    int n2 = (int)(pair % (NN / 2));
    size_t row = pair / (NN / 2);
    int t = (int)(row % TT);

    const float inv2pi = 0.15915494309189535f;
    float freq = exp2f(-(float)(n2 * 2) * (1.0f / 256.0f)) * inv2pi;
    float ph = (float)t * freq;
    float fr = ph - floorf(ph);
    float s, c;
    sincospif(2.0f * fr, &s, &c);

    float2 v = ((const float2*)Q)[pair];
    float ox = v.x * c - v.y * s;
    float oy = v.y * c + v.x * s;

    __nv_bfloat16 hx, lx, hy, ly;
    split2(ox, hx, lx);
    split2(oy, hy, ly);
    __nv_bfloat162 ph2; ph2.x = hx; ph2.y = hy;
    __nv_bfloat162 pl2; pl2.x = lx; pl2.y = ly;
    ((__nv_bfloat162*)g_QRh)[pair] = ph2;
    ((__nv_bfloat162*)g_QRl)[pair] = pl2;
}

// ---------------------------------------------------------------------------
// Kernel 2: hi/lo bf16 split of V
// ---------------------------------------------------------------------------
__global__ void v_split(const float* __restrict__ V) {
    size_t i = ((size_t)blockIdx.x * blockDim.x + threadIdx.x) * 4;
    float4 v = *(const float4*)(V + i);
    __nv_bfloat16 h0, l0, h1, l1, h2, l2, h3, l3;
    split2(v.x, h0, l0); split2(v.y, h1, l1);
    split2(v.z, h2, l2); split2(v.w, h3, l3);
    __nv_bfloat162 a, b;
    a.x = h0; a.y = h1; b.x = h2; b.y = h3;
    ((__nv_bfloat162*)g_Vh)[i / 2] = a;
    ((__nv_bfloat162*)g_Vh)[i / 2 + 1] = b;
    a.x = l0; a.y = l1; b.x = l2; b.y = l3;
    ((__nv_bfloat162*)g_Vl)[i / 2] = a;
    ((__nv_bfloat162*)g_Vl)[i / 2 + 1] = b;
}

// ---------------------------------------------------------------------------
// Kernel 3: S = scale * QR @ QR^T  (3-term bf16 split, upper-tri blocks only,
// mirror written via smem transpose). Output split into Sh/Sl bf16.
// ---------------------------------------------------------------------------
__global__ __launch_bounds__(256) void gemm1() {
    const int h = blockIdx.y;
    int u = blockIdx.x, br = 0;
    while (u >= 16 - br) { u -= 16 - br; br++; }
    const int bc = br + u;
    const int row0 = br * 128, col0 = bc * 128;

    const __nv_bfloat16* __restrict__ Qh = g_QRh + (size_t)h * TT * NN;
    const __nv_bfloat16* __restrict__ Ql = g_QRl + (size_t)h * TT * NN;

    __shared__ __nv_bfloat16 sm[4][128][AP];   // [0]=Ah [1]=Al [2]=Bh [3]=Bl

    const int tid = threadIdx.x;
    const int lr = tid >> 1;            // 0..127
    const int lcb = (tid & 1) * 16;     // 0 or 16
    const int lane = tid & 31, wid = tid >> 5;
    const int wm = (wid >> 2) * 64, wn = (wid & 3) * 32;
    const int mi = lane >> 3, r8 = lane & 7;
    const int q = lane & 3, l4 = lane >> 2;

    float acc[4][4][4];
#pragma unroll
    for (int a = 0; a < 4; a++)
#pragma unroll
        for (int b = 0; b < 4; b++)
#pragma unroll
            for (int cc = 0; cc < 4; cc++) acc[a][b][cc] = 0.0f;

    for (int k0 = 0; k0 < NN; k0 += 32) {
        const uint4* pAh = (const uint4*)(Qh + (size_t)(row0 + lr) * NN + k0 + lcb);
        const uint4* pAl = (const uint4*)(Ql + (size_t)(row0 + lr) * NN + k0 + lcb);
        const uint4* pBh = (const uint4*)(Qh + (size_t)(col0 + lr) * NN + k0 + lcb);
        const uint4* pBl = (const uint4*)(Ql + (size_t)(col0 + lr) * NN + k0 + lcb);
        uint4 ah0 = pAh[0], ah1 = pAh[1];
        uint4 al0 = pAl[0], al1 = pAl[1];
        uint4 bh0 = pBh[0], bh1 = pBh[1];
        uint4 bl0 = pBl[0], bl1 = pBl[1];
        __syncthreads();
        *(uint4*)&sm[0][lr][lcb] = ah0; *(uint4*)&sm[0][lr][lcb + 8] = ah1;
        *(uint4*)&sm[1][lr][lcb] = al0; *(uint4*)&sm[1][lr][lcb + 8] = al1;
        *(uint4*)&sm[2][lr][lcb] = bh0; *(uint4*)&sm[2][lr][lcb + 8] = bh1;
        *(uint4*)&sm[3][lr][lcb] = bl0; *(uint4*)&sm[3][lr][lcb + 8] = bl1;
        __syncthreads();

#pragma unroll
        for (int kk = 0; kk < 32; kk += 16) {
            uint32_t fbh[4][2], fbl[4][2];
#pragma unroll
            for (int p = 0; p < 2; p++) {
                uint32_t r[4];
                ldsm4(r, smaddr(&sm[2][wn + p * 16 + (mi >> 1) * 8 + r8][kk + (mi & 1) * 8]));
                fbh[p * 2][0] = r[0]; fbh[p * 2][1] = r[1];
                fbh[p * 2 + 1][0] = r[2]; fbh[p * 2 + 1][1] = r[3];
                ldsm4(r, smaddr(&sm[3][wn + p * 16 + (mi >> 1) * 8 + r8][kk + (mi & 1) * 8]));
                fbl[p * 2][0] = r[0]; fbl[p * 2][1] = r[1];
                fbl[p * 2 + 1][0] = r[2]; fbl[p * 2 + 1][1] = r[3];
            }
#pragma unroll
            for (int mt = 0; mt < 4; mt++) {
                uint32_t fah[4], fal[4];
                ldsm4(fah, smaddr(&sm[0][wm + mt * 16 + (mi & 1) * 8 + r8][kk + (mi >> 1) * 8]));
                ldsm4(fal, smaddr(&sm[1][wm + mt * 16 + (mi & 1) * 8 + r8][kk + (mi >> 1) * 8]));
#pragma unroll
                for (int nt = 0; nt < 4; nt++) {
                    mma16816(acc[mt][nt], fah, fbh[nt]);
                    mma16816(acc[mt][nt], fah, fbl[nt]);
                    mma16816(acc[mt][nt], fal, fbh[nt]);
                }
            }
        }
    }

    const float scale = 1.0f / 64.0f;
    __nv_bfloat16* Sh = g_Sh + (size_t)h * TT * TT;
    __nv_bfloat16* Sl = g_Sl + (size_t)h * TT * TT;

    // direct writes
#pragma unroll
    for (int mt = 0; mt < 4; mt++)
#pragma unroll
        for (int nt = 0; nt < 4; nt++) {
            int c = col0 + wn + nt * 8 + q * 2;
#pragma unroll
            for (int hh = 0; hh < 2; hh++) {
                int r = row0 + wm + mt * 16 + l4 + hh * 8;
                float x0 = acc[mt][nt][hh * 2 + 0] * scale;
                float x1 = acc[mt][nt][hh * 2 + 1] * scale;
                __nv_bfloat16 h0, l0, h1, l1;
                split2(x0, h0, l0); split2(x1, h1, l1);
                __nv_bfloat162 ph; ph.x = h0; ph.y = h1;
                __nv_bfloat162 pl; pl.x = l0; pl.y = l1;
                *(__nv_bfloat162*)&Sh[(size_t)r * TT + c] = ph;
                *(__nv_bfloat162*)&Sl[(size_t)r * TT + c] = pl;
            }
        }

    // mirror (transpose) writes for off-diagonal blocks
    if (br != bc) {
        __nv_bfloat16* ts = &sm[0][0][0];   // 128 x BPITCH fits in 4*128*AP
#pragma unroll
        for (int sel = 0; sel < 2; sel++) {
            __syncthreads();
#pragma unroll
            for (int mt = 0; mt < 4; mt++)
#pragma unroll
                for (int nt = 0; nt < 4; nt++)
#pragma unroll
                    for (int hh = 0; hh < 2; hh++) {
                        int rl = wm + mt * 16 + l4 + hh * 8;
                        int cl = wn + nt * 8 + q * 2;
                        float x0 = acc[mt][nt][hh * 2 + 0] * scale;
                        float x1 = acc[mt][nt][hh * 2 + 1] * scale;
                        __nv_bfloat16 v0, v1;
                        if (sel == 0) {
                            v0 = __float2bfloat16(x0);
                            v1 = __float2bfloat16(x1);
                        } else {
                            __nv_bfloat16 t0 = __float2bfloat16(x0);
                            __nv_bfloat16 t1 = __float2bfloat16(x1);
                            v0 = __float2bfloat16(x0 - __bfloat162float(t0));
                            v1 = __float2bfloat16(x1 - __bfloat162float(t1));
                        }
                        ts[(size_t)cl * BPITCH + rl] = v0;
                        ts[(size_t)(cl + 1) * BPITCH + rl] = v1;
                    }
            __syncthreads();
            __nv_bfloat16* dst = sel ? Sl : Sh;
            int cr = tid >> 1, cb2 = (tid & 1) * 64;
#pragma unroll
            for (int j = 0; j < 8; j++) {   // FIX: 8 x uint4 = 64 elems (was 4 -> half-written mirror tiles)
                uint4 v = *(uint4*)&ts[(size_t)cr * BPITCH + cb2 + j * 8];
                *(uint4*)&dst[(size_t)(col0 + cr) * TT + row0 + cb2 + j * 8] = v;
            }
        }
    }
}

// ---------------------------------------------------------------------------
// Kernel 4: O = S @ V  (3-term bf16 split, NN gemm)
// ---------------------------------------------------------------------------
__global__ __launch_bounds__(256) void gemm2(float* __restrict__ O) {
    const int h = blockIdx.z;
    const int col0 = blockIdx.x * 128, row0 = blockIdx.y * 128;

    const __nv_bfloat16* __restrict__ Sh = g_Sh + (size_t)h * TT * TT;
    const __nv_bfloat16* __restrict__ Sl = g_Sl + (size_t)h * TT * TT;
    const __nv_bfloat16* __restrict__ Vh = g_Vh + (size_t)h * TT * NN;
    const __nv_bfloat16* __restrict__ Vl = g_Vl + (size_t)h * TT * NN;
    float* __restrict__ Oh = O + (size_t)h * TT * NN;

    __shared__ __nv_bfloat16 smA[2][128][AP];       // [0]=Sh [1]=Sl
    __shared__ __nv_bfloat16 smB[2][32][BPITCH];    // [0]=Vh [1]=Vl

    const int tid = threadIdx.x;
    const int lr = tid >> 1;
    const int lcb = (tid & 1) * 16;
    const int kr = tid >> 3;           // 0..31
    const int cb = (tid & 7) * 16;     // 0..112
    const int lane = tid & 31, wid = tid >> 5;
    const int wm = (wid >> 2) * 64, wn = (wid & 3) * 32;
    const int mi = lane >> 3, r8 = lane & 7;
    const int q = lane & 3, l4 = lane >> 2;

    float acc[4][4][4];
#pragma unroll
    for (int a = 0; a < 4; a++)
#pragma unroll
        for (int b = 0; b < 4; b++)
#pragma unroll
            for (int cc = 0; cc < 4; cc++) acc[a][b][cc] = 0.0f;

    for (int k0 = 0; k0 < TT; k0 += 32) {
        const uint4* pAh = (const uint4*)(Sh + (size_t)(row0 + lr) * TT + k0 + lcb);
        const uint4* pAl = (const uint4*)(Sl + (size_t)(row0 + lr) * TT + k0 + lcb);
        const uint4* pBh = (const uint4*)(Vh + (size_t)(k0 + kr) * NN + col0 + cb);
        const uint4* pBl = (const uint4*)(Vl + (size_t)(k0 + kr) * NN + col0 + cb);
        uint4 ah0 = pAh[0], ah1 = pAh[1];
        uint4 al0 = pAl[0], al1 = pAl[1];
        uint4 bh0 = pBh[0], bh1 = pBh[1];
        uint4 bl0 = pBl[0], bl1 = pBl[1];
        __syncthreads();
        *(uint4*)&smA[0][lr][lcb] = ah0; *(uint4*)&smA[0][lr][lcb + 8] = ah1;
        *(uint4*)&smA[1][lr][lcb] = al0; *(uint4*)&smA[1][lr][lcb + 8] = al1;
        *(uint4*)&smB[0][kr][cb] = bh0; *(uint4*)&smB[0][kr][cb + 8] = bh1;
        *(uint4*)&smB[1][kr][cb] = bl0; *(uint4*)&smB[1][kr][cb + 8] = bl1;
        __syncthreads();

#pragma unroll
        for (int kk = 0; kk < 32; kk += 16) {
            uint32_t fbh[4][2], fbl[4][2];
#pragma unroll
            for (int p = 0; p < 2; p++) {
                uint32_t r[4];
                ldsm4t(r, smaddr(&smB[0][kk + (mi & 1) * 8 + r8][wn + p * 16 + (mi >> 1) * 8]));
                fbh[p * 2][0] = r[0]; fbh[p * 2][1] = r[1];
                fbh[p * 2 + 1][0] = r[2]; fbh[p * 2 + 1][1] = r[3];
                ldsm4t(r, smaddr(&smB[1][kk + (mi & 1) * 8 + r8][wn + p * 16 + (mi >> 1) * 8]));
                fbl[p * 2][0] = r[0]; fbl[p * 2][1] = r[1];
                fbl[p * 2 + 1][0] = r[2]; fbl[p * 2 + 1][1] = r[3];
            }
#pragma unroll
            for (int mt = 0; mt < 4; mt++) {
                uint32_t fah[4], fal[4];
                ldsm4(fah, smaddr(&smA[0][wm + mt * 16 + (mi & 1) * 8 + r8][kk + (mi >> 1) * 8]));
                ldsm4(fal, smaddr(&smA[1][wm + mt * 16 + (mi & 1) * 8 + r8][kk + (mi >> 1) * 8]));
#pragma unroll
                for (int nt = 0; nt < 4; nt++) {
                    mma16816(acc[mt][nt], fah, fbh[nt]);
                    mma16816(acc[mt][nt], fah, fbl[nt]);
                    mma16816(acc[mt][nt], fal, fbh[nt]);
                }
            }
        }
    }

#pragma unroll
    for (int mt = 0; mt < 4; mt++)
#pragma unroll
        for (int nt = 0; nt < 4; nt++) {
            int c = col0 + wn + nt * 8 + q * 2;
#pragma unroll
            for (int hh = 0; hh < 2; hh++) {
                int r = row0 + wm + mt * 16 + l4 + hh * 8;
                *(float2*)&Oh[(size_t)r * NN + c] =
                    make_float2(acc[mt][nt][hh * 2 + 0], acc[mt][nt][hh * 2 + 1]);
            }
        }
}

// ---------------------------------------------------------------------------
// Launch
// ---------------------------------------------------------------------------
extern "C" void kernel_launch(void* const* d_in, const int* in_sizes, int n_in,
                              void* d_out, int out_size) {
    const float* Q = (const float*)d_in[0];
    const float* V = (const float*)d_in[2];
    float* O = (float*)d_out;

    {   // RoPE + split: 33,554,432 pairs
        int threads = 256;
        int blocks = (int)(((size_t)NHT * TT * NN / 2) / threads);
        rope_split<<<blocks, threads>>>(Q);
    }
    {   // V split: 67,108,864 elems / 4 per thread
        int threads = 256;
        int blocks = (int)(((size_t)NHT * TT * NN / 4) / threads);
        v_split<<<blocks, threads>>>(V);
    }
    {   // S = scale * QR QR^T (upper-tri blocks: 16*17/2 = 136)
        dim3 grid(136, NHT);
        gemm1<<<grid, 256>>>();
    }
    {   // O = S V
        dim3 grid(NN / 128, TT / 128, NHT);
        gemm2<<<grid, 256>>>(O);
    }
}

// round 5
// speedup vs baseline: 4.6266x; 1.7350x over previous
#include <cuda_runtime.h>
#include <cuda_fp16.h>
#include <cstdint>

#define TT 2048
#define NN 4096
#define NHT 8
#define AP 40        // half pitch for 32-wide K tiles (80B rows, conflict-free LDSM)
#define BPITCH 136   // half pitch for 128-wide tiles (272B rows, conflict-free LDSM.T)
#define TRPITCH 136

// fp16 hi/lo scratch (allocation-free device globals)
__device__ __align__(128) __half g_QRh[(size_t)NHT * TT * NN];
__device__ __align__(128) __half g_QRl[(size_t)NHT * TT * NN];
__device__ __align__(128) __half g_Vh[(size_t)NHT * TT * NN];
__device__ __align__(128) __half g_Sh[(size_t)NHT * TT * TT];
__device__ __align__(128) __half g_Sl[(size_t)NHT * TT * TT];

__device__ __forceinline__ uint32_t smaddr(const void* p) {
    return (uint32_t)__cvta_generic_to_shared(p);
}
__device__ __forceinline__ void ldsm4(uint32_t* r, uint32_t a) {
    asm volatile("ldmatrix.sync.aligned.m8n8.x4.shared.b16 {%0,%1,%2,%3},[%4];"
                 : "=r"(r[0]), "=r"(r[1]), "=r"(r[2]), "=r"(r[3]) : "r"(a));
}
__device__ __forceinline__ void ldsm4t(uint32_t* r, uint32_t a) {
    asm volatile("ldmatrix.sync.aligned.m8n8.x4.trans.shared.b16 {%0,%1,%2,%3},[%4];"
                 : "=r"(r[0]), "=r"(r[1]), "=r"(r[2]), "=r"(r[3]) : "r"(a));
}
__device__ __forceinline__ void mmaf16(float* d, const uint32_t* a, const uint32_t* b) {
    asm volatile("mma.sync.aligned.m16n8k16.row.col.f32.f16.f16.f32 "
                 "{%0,%1,%2,%3},{%4,%5,%6,%7},{%8,%9},{%0,%1,%2,%3};"
                 : "+f"(d[0]), "+f"(d[1]), "+f"(d[2]), "+f"(d[3])
                 : "r"(a[0]), "r"(a[1]), "r"(a[2]), "r"(a[3]), "r"(b[0]), "r"(b[1]));
}
__device__ __forceinline__ void split2h(float x, __half& h, __half& l) {
    h = __float2half_rn(x);
    l = __float2half_rn(x - __half2float(h));
}
__device__ __forceinline__ void cpa16(uint32_t dst, const void* src) {
    asm volatile("cp.async.cg.shared.global [%0],[%1],16;" :: "r"(dst), "l"(src));
}
__device__ __forceinline__ void cp_commit() { asm volatile("cp.async.commit_group;" ::: "memory"); }
template <int N> __device__ __forceinline__ void cp_wait() {
    asm volatile("cp.async.wait_group %0;" :: "n"(N) : "memory");
}

// ---------------------------------------------------------------------------
// Kernel 1: RoPE + fp16 hi/lo split of QR
// ---------------------------------------------------------------------------
__global__ void rope_split(const float* __restrict__ Q) {
    size_t pair = (size_t)blockIdx.x * blockDim.x + threadIdx.x;
    int n2 = (int)(pair % (NN / 2));
    size_t row = pair / (NN / 2);
    int t = (int)(row % TT);

    const float inv2pi = 0.15915494309189535f;
    float freq = exp2f(-(float)(n2 * 2) * (1.0f / 256.0f)) * inv2pi;
    float ph = (float)t * freq;
    float fr = ph - floorf(ph);
    float s, c;
    sincospif(2.0f * fr, &s, &c);

    float2 v = ((const float2*)Q)[pair];
    float ox = v.x * c - v.y * s;
    float oy = v.y * c + v.x * s;

    __half hx, lx, hy, ly;
    split2h(ox, hx, lx);
    split2h(oy, hy, ly);
    __half2 a = __halves2half2(hx, hy);
    __half2 b = __halves2half2(lx, ly);
    ((__half2*)g_QRh)[pair] = a;
    ((__half2*)g_QRl)[pair] = b;
}

// ---------------------------------------------------------------------------
// Kernel 2: V -> fp16 (hi only; dropped S_h*V_l term is ~1.4e-4 relative)
// ---------------------------------------------------------------------------
__global__ void v_half(const float* __restrict__ V) {
    size_t i = ((size_t)blockIdx.x * blockDim.x + threadIdx.x) * 8;
    float4 v0 = *(const float4*)(V + i);
    float4 v1 = *(const float4*)(V + i + 4);
    __half2 o[4];
    o[0] = __halves2half2(__float2half_rn(v0.x), __float2half_rn(v0.y));
    o[1] = __halves2half2(__float2half_rn(v0.z), __float2half_rn(v0.w));
    o[2] = __halves2half2(__float2half_rn(v1.x), __float2half_rn(v1.y));
    o[3] = __halves2half2(__float2half_rn(v1.z), __float2half_rn(v1.w));
    *(uint4*)(g_Vh + i) = *(uint4*)o;
}

// ---------------------------------------------------------------------------
// Kernel 3: S = scale * QR QR^T  (fp16 2-term: Qh*Qh + Ql*Qh; upper-tri only)
// smem: 3 stages x {Ah[128][AP], Al[128][AP], Bh[128][AP]}
// ---------------------------------------------------------------------------
#define G1_STAGE_H 15360        // halves per stage (3 * 128*40)
#define G1_DSMEM (3 * G1_STAGE_H * 2)

__global__ __launch_bounds__(256, 2) void gemm1(void) {
    extern __shared__ __align__(16) __half sm[];
    const uint32_t smb = smaddr(sm);

    const int h = blockIdx.y;
    int u = blockIdx.x, br = 0;
    while (u >= 16 - br) { u -= 16 - br; br++; }
    const int bc = br + u;
    const int row0 = br * 128, col0 = bc * 128;

    const __half* __restrict__ Qh = g_QRh + (size_t)h * TT * NN;
    const __half* __restrict__ Ql = g_QRl + (size_t)h * TT * NN;

    const int tid = threadIdx.x;
    const int lane = tid & 31, wid = tid >> 5;
    const int wm = (wid >> 2) * 64, wn = (wid & 3) * 32;
    const int mi = lane >> 3, r8 = lane & 7;
    const int q = lane & 3, l4 = lane >> 2;

    // loader: 1536 chunks of 16B per stage, 6 per thread
    auto load = [&](int stg, int k0) {
        const uint32_t sb = smb + (uint32_t)stg * G1_STAGE_H * 2;
#pragma unroll
        for (int it = 0; it < 6; it++) {
            int c = it * 256 + tid;
            int t = c >> 9;               // 0:Ah 1:Al 2:Bh
            int rr = (c & 511) >> 2;
            int kg = c & 3;
            const __half* src =
                (t == 0 ? Qh + (size_t)(row0 + rr) * NN
                 : t == 1 ? Ql + (size_t)(row0 + rr) * NN
                          : Qh + (size_t)(col0 + rr) * NN) + k0 + kg * 8;
            cpa16(sb + (uint32_t)(t * 5120 + rr * AP + kg * 8) * 2, src);
        }
        cp_commit();
    };

    float acc[4][4][4];
#pragma unroll
    for (int a = 0; a < 4; a++)
#pragma unroll
        for (int b = 0; b < 4; b++)
#pragma unroll
            for (int cc = 0; cc < 4; cc++) acc[a][b][cc] = 0.0f;

    const int NS = NN / 32;
    load(0, 0);
    load(1, 32);

    for (int s = 0; s < NS; s++) {
        if (s + 1 < NS) cp_wait<1>(); else cp_wait<0>();
        __syncthreads();
        const __half* st = sm + (size_t)(s % 3) * G1_STAGE_H;
        const __half* sAh = st;
        const __half* sAl = st + 5120;
        const __half* sBh = st + 10240;
#pragma unroll
        for (int kk = 0; kk < 32; kk += 16) {
            uint32_t fbh[4][2];
#pragma unroll
            for (int p = 0; p < 2; p++) {
                uint32_t r[4];
                ldsm4(r, smaddr(sBh + (size_t)(wn + p * 16 + (mi >> 1) * 8 + r8) * AP + kk + (mi & 1) * 8));
                fbh[p * 2][0] = r[0]; fbh[p * 2][1] = r[1];
                fbh[p * 2 + 1][0] = r[2]; fbh[p * 2 + 1][1] = r[3];
            }
#pragma unroll
            for (int mt = 0; mt < 4; mt++) {
                uint32_t fah[4], fal[4];
                ldsm4(fah, smaddr(sAh + (size_t)(wm + mt * 16 + (mi & 1) * 8 + r8) * AP + kk + (mi >> 1) * 8));
                ldsm4(fal, smaddr(sAl + (size_t)(wm + mt * 16 + (mi & 1) * 8 + r8) * AP + kk + (mi >> 1) * 8));
#pragma unroll
                for (int nt = 0; nt < 4; nt++) {
                    mmaf16(acc[mt][nt], fah, fbh[nt]);
                    mmaf16(acc[mt][nt], fal, fbh[nt]);
                }
            }
        }
        if (s + 2 < NS) load((s + 2) % 3, (s + 2) * 32);
    }

    const float scale = 1.0f / 64.0f;
    __half* Sh = g_Sh + (size_t)h * TT * TT;
    __half* Sl = g_Sl + (size_t)h * TT * TT;
    const bool mirror = (br != bc);

    // direct writes
#pragma unroll
    for (int mt = 0; mt < 4; mt++)
#pragma unroll
        for (int nt = 0; nt < 4; nt++) {
            int c = col0 + wn + nt * 8 + q * 2;
#pragma unroll
            for (int hh = 0; hh < 2; hh++) {
                int r = row0 + wm + mt * 16 + l4 + hh * 8;
                float x0 = acc[mt][nt][hh * 2 + 0] * scale;
                float x1 = acc[mt][nt][hh * 2 + 1] * scale;
                __half h0, l0, h1, l1;
                split2h(x0, h0, l0); split2h(x1, h1, l1);
                *(__half2*)&Sh[(size_t)r * TT + c] = __halves2half2(h0, h1);
                *(__half2*)&Sl[(size_t)r * TT + c] = __halves2half2(l0, l1);
            }
        }

    // mirror writes via smem transpose
    if (mirror) {
        __syncthreads();   // done with pipeline smem
        __half* tsh = sm;
        __half* tsl = sm + 128 * TRPITCH;
#pragma unroll
        for (int mt = 0; mt < 4; mt++)
#pragma unroll
            for (int nt = 0; nt < 4; nt++)
#pragma unroll
                for (int hh = 0; hh < 2; hh++) {
                    int rl = wm + mt * 16 + l4 + hh * 8;
                    int cl = wn + nt * 8 + q * 2;
                    float x0 = acc[mt][nt][hh * 2 + 0] * scale;
                    float x1 = acc[mt][nt][hh * 2 + 1] * scale;
                    __half h0, l0, h1, l1;
                    split2h(x0, h0, l0); split2h(x1, h1, l1);
                    tsh[(size_t)cl * TRPITCH + rl] = h0;
                    tsh[(size_t)(cl + 1) * TRPITCH + rl] = h1;
                    tsl[(size_t)cl * TRPITCH + rl] = l0;
                    tsl[(size_t)(cl + 1) * TRPITCH + rl] = l1;
                }
        __syncthreads();
        int cr = tid >> 1, cb2 = (tid & 1) * 64;
        size_t base = (size_t)(col0 + cr) * TT + row0 + cb2;
#pragma unroll
        for (int j = 0; j < 8; j++) {
            *(uint4*)&Sh[base + j * 8] = *(uint4*)&tsh[(size_t)cr * TRPITCH + cb2 + j * 8];
            *(uint4*)&Sl[base + j * 8] = *(uint4*)&tsl[(size_t)cr * TRPITCH + cb2 + j * 8];
        }
    }
}

// ---------------------------------------------------------------------------
// Kernel 4: O = S V  (fp16 2-term: Sh*Vh + Sl*Vh)
// smem: 3 stages x {Ah[128][AP], Al[128][AP], B[32][BPITCH]}
// ---------------------------------------------------------------------------
#define G2_STAGE_H 14592        // 5120 + 5120 + 32*136
#define G2_DSMEM (3 * G2_STAGE_H * 2)

__global__ __launch_bounds__(256, 2) void gemm2(float* __restrict__ O) {
    extern __shared__ __align__(16) __half sm[];
    const uint32_t smb = smaddr(sm);

    const int h = blockIdx.z;
    const int col0 = blockIdx.x * 128, row0 = blockIdx.y * 128;

    const __half* __restrict__ Sh = g_Sh + (size_t)h * TT * TT;
    const __half* __restrict__ Sl = g_Sl + (size_t)h * TT * TT;
    const __half* __restrict__ Vh = g_Vh + (size_t)h * TT * NN;
    float* __restrict__ Oh = O + (size_t)h * TT * NN;

    const int tid = threadIdx.x;
    const int lane = tid & 31, wid = tid >> 5;
    const int wm = (wid >> 2) * 64, wn = (wid & 3) * 32;
    const int mi = lane >> 3, r8 = lane & 7;
    const int q = lane & 3, l4 = lane >> 2;

    auto load = [&](int stg, int k0) {
        const uint32_t sb = smb + (uint32_t)stg * G2_STAGE_H * 2;
#pragma unroll
        for (int it = 0; it < 6; it++) {
            int c = it * 256 + tid;
            int t = c >> 9;
            int c2 = c & 511;
            if (t < 2) {
                int rr = c2 >> 2, kg = c2 & 3;
                const __half* src = (t == 0 ? Sh : Sl) + (size_t)(row0 + rr) * TT + k0 + kg * 8;
                cpa16(sb + (uint32_t)(t * 5120 + rr * AP + kg * 8) * 2, src);
            } else {
                int rr = c2 >> 4, cg = c2 & 15;
                const __half* src = Vh + (size_t)(k0 + rr) * NN + col0 + cg * 8;
                cpa16(sb + (uint32_t)(10240 + rr * BPITCH + cg * 8) * 2, src);
            }
        }
        cp_commit();
    };

    float acc[4][4][4];
#pragma unroll
    for (int a = 0; a < 4; a++)
#pragma unroll
        for (int b = 0; b < 4; b++)
#pragma unroll
            for (int cc = 0; cc < 4; cc++) acc[a][b][cc] = 0.0f;

    const int NS = TT / 32;
    load(0, 0);
    load(1, 32);

    for (int s = 0; s < NS; s++) {
        if (s + 1 < NS) cp_wait<1>(); else cp_wait<0>();
        __syncthreads();
        const __half* st = sm + (size_t)(s % 3) * G2_STAGE_H;
        const __half* sAh = st;
        const __half* sAl = st + 5120;
        const __half* sB = st + 10240;
#pragma unroll
        for (int kk = 0; kk < 32; kk += 16) {
            uint32_t fbh[4][2];
#pragma unroll
            for (int p = 0; p < 2; p++) {
                uint32_t r[4];
                ldsm4t(r, smaddr(sB + (size_t)(kk + (mi & 1) * 8 + r8) * BPITCH + wn + p * 16 + (mi >> 1) * 8));
                fbh[p * 2][0] = r[0]; fbh[p * 2][1] = r[1];
                fbh[p * 2 + 1][0] = r[2]; fbh[p * 2 + 1][1] = r[3];
            }
#pragma unroll
            for (int mt = 0; mt < 4; mt++) {
                uint32_t fah[4], fal[4];
                ldsm4(fah, smaddr(sAh + (size_t)(wm + mt * 16 + (mi & 1) * 8 + r8) * AP + kk + (mi >> 1) * 8));
                ldsm4(fal, smaddr(sAl + (size_t)(wm + mt * 16 + (mi & 1) * 8 + r8) * AP + kk + (mi >> 1) * 8));
#pragma unroll
                for (int nt = 0; nt < 4; nt++) {
                    mmaf16(acc[mt][nt], fah, fbh[nt]);
                    mmaf16(acc[mt][nt], fal, fbh[nt]);
                }
            }
        }
        if (s + 2 < NS) load((s + 2) % 3, (s + 2) * 32);
    }

#pragma unroll
    for (int mt = 0; mt < 4; mt++)
#pragma unroll
        for (int nt = 0; nt < 4; nt++) {
            int c = col0 + wn + nt * 8 + q * 2;
#pragma unroll
            for (int hh = 0; hh < 2; hh++) {
                int r = row0 + wm + mt * 16 + l4 + hh * 8;
                *(float2*)&Oh[(size_t)r * NN + c] =
                    make_float2(acc[mt][nt][hh * 2 + 0], acc[mt][nt][hh * 2 + 1]);
            }
        }
}

// ---------------------------------------------------------------------------
// Launch
// ---------------------------------------------------------------------------
extern "C" void kernel_launch(void* const* d_in, const int* in_sizes, int n_in,
                              void* d_out, int out_size) {
    const float* Q = (const float*)d_in[0];
    const float* V = (const float*)d_in[2];
    float* O = (float*)d_out;

    cudaFuncSetAttribute(gemm1, cudaFuncAttributeMaxDynamicSharedMemorySize, G1_DSMEM);
    cudaFuncSetAttribute(gemm2, cudaFuncAttributeMaxDynamicSharedMemorySize, G2_DSMEM);

    {   // RoPE + fp16 split
        int threads = 256;
        int blocks = (int)(((size_t)NHT * TT * NN / 2) / threads);
        rope_split<<<blocks, threads>>>(Q);
    }
    {   // V -> fp16
        int threads = 256;
        int blocks = (int)(((size_t)NHT * TT * NN / 8) / threads);
        v_half<<<blocks, threads>>>(V);
    }
    {   // S = scale * QR QR^T (136 upper-tri tiles per head)
        dim3 grid(136, NHT);
        gemm1<<<grid, 256, G1_DSMEM>>>();
    }
    {   // O = S V
        dim3 grid(NN / 128, TT / 128, NHT);
        gemm2<<<grid, 256, G2_DSMEM>>>(O);
    }
}

// round 6
// speedup vs baseline: 6.2049x; 1.3411x over previous
#include <cuda_runtime.h>
#include <cuda_fp16.h>
#include <cstdint>

#define TT 2048
#define NN 4096
#define NHT 8
#define AP 40        // half pitch for 32-wide K tiles (80B rows, conflict-free LDSM)
#define BPITCH 136   // half pitch for 128-wide tiles (272B rows, conflict-free LDSM.T)
#define TRPITCH 136

// fp16 scratch (allocation-free device globals)
__device__ __align__(128) __half g_QRh[(size_t)NHT * TT * NN];
__device__ __align__(128) __half g_QRl[(size_t)NHT * TT * NN];
__device__ __align__(128) __half g_Vh[(size_t)NHT * TT * NN];
__device__ __align__(128) __half g_Sh[(size_t)NHT * TT * TT];

__device__ __forceinline__ uint32_t smaddr(const void* p) {
    return (uint32_t)__cvta_generic_to_shared(p);
}
__device__ __forceinline__ void ldsm4(uint32_t* r, uint32_t a) {
    asm volatile("ldmatrix.sync.aligned.m8n8.x4.shared.b16 {%0,%1,%2,%3},[%4];"
                 : "=r"(r[0]), "=r"(r[1]), "=r"(r[2]), "=r"(r[3]) : "r"(a));
}
__device__ __forceinline__ void ldsm4t(uint32_t* r, uint32_t a) {
    asm volatile("ldmatrix.sync.aligned.m8n8.x4.trans.shared.b16 {%0,%1,%2,%3},[%4];"
                 : "=r"(r[0]), "=r"(r[1]), "=r"(r[2]), "=r"(r[3]) : "r"(a));
}
__device__ __forceinline__ void mmaf16(float* d, const uint32_t* a, const uint32_t* b) {
    asm volatile("mma.sync.aligned.m16n8k16.row.col.f32.f16.f16.f32 "
                 "{%0,%1,%2,%3},{%4,%5,%6,%7},{%8,%9},{%0,%1,%2,%3};"
                 : "+f"(d[0]), "+f"(d[1]), "+f"(d[2]), "+f"(d[3])
                 : "r"(a[0]), "r"(a[1]), "r"(a[2]), "r"(a[3]), "r"(b[0]), "r"(b[1]));
}
__device__ __forceinline__ void split2h(float x, __half& h, __half& l) {
    h = __float2half_rn(x);
    l = __float2half_rn(x - __half2float(h));
}
__device__ __forceinline__ void cpa16(uint32_t dst, const void* src) {
    asm volatile("cp.async.cg.shared.global [%0],[%1],16;" :: "r"(dst), "l"(src));
}
__device__ __forceinline__ void cp_commit() { asm volatile("cp.async.commit_group;" ::: "memory"); }
template <int N> __device__ __forceinline__ void cp_wait() {
    asm volatile("cp.async.wait_group %0;" :: "n"(N) : "memory");
}

// ---------------------------------------------------------------------------
// Kernel 1: RoPE + fp16 hi/lo split of QR
// ---------------------------------------------------------------------------
__global__ void rope_split(const float* __restrict__ Q) {
    size_t pair = (size_t)blockIdx.x * blockDim.x + threadIdx.x;
    int n2 = (int)(pair % (NN / 2));
    size_t row = pair / (NN / 2);
    int t = (int)(row % TT);

    const float inv2pi = 0.15915494309189535f;
    float freq = exp2f(-(float)(n2 * 2) * (1.0f / 256.0f)) * inv2pi;
    float ph = (float)t * freq;
    float fr = ph - floorf(ph);
    float s, c;
    sincospif(2.0f * fr, &s, &c);

    float2 v = ((const float2*)Q)[pair];
    float ox = v.x * c - v.y * s;
    float oy = v.y * c + v.x * s;

    __half hx, lx, hy, ly;
    split2h(ox, hx, lx);
    split2h(oy, hy, ly);
    ((__half2*)g_QRh)[pair] = __halves2half2(hx, hy);
    ((__half2*)g_QRl)[pair] = __halves2half2(lx, ly);
}

// ---------------------------------------------------------------------------
// Kernel 2: V -> fp16
// ---------------------------------------------------------------------------
__global__ void v_half(const float* __restrict__ V) {
    size_t i = ((size_t)blockIdx.x * blockDim.x + threadIdx.x) * 8;
    float4 v0 = *(const float4*)(V + i);
    float4 v1 = *(const float4*)(V + i + 4);
    __half2 o[4];
    o[0] = __halves2half2(__float2half_rn(v0.x), __float2half_rn(v0.y));
    o[1] = __halves2half2(__float2half_rn(v0.z), __float2half_rn(v0.w));
    o[2] = __halves2half2(__float2half_rn(v1.x), __float2half_rn(v1.y));
    o[3] = __halves2half2(__float2half_rn(v1.z), __float2half_rn(v1.w));
    *(uint4*)(g_Vh + i) = *(uint4*)o;
}

// ---------------------------------------------------------------------------
// Kernel 3: S = scale * QR QR^T  (2-term: Qh*Qh + Ql*Qh; upper-tri only;
// output fp16 Sh only)
// ---------------------------------------------------------------------------
#define G1_STAGE_H 15360        // halves per stage (3 * 128*40)
#define G1_DSMEM (3 * G1_STAGE_H * 2)

__global__ __launch_bounds__(256, 2) void gemm1(void) {
    extern __shared__ __align__(16) __half sm[];
    const uint32_t smb = smaddr(sm);

    const int h = blockIdx.y;
    int u = blockIdx.x, br = 0;
    while (u >= 16 - br) { u -= 16 - br; br++; }
    const int bc = br + u;
    const int row0 = br * 128, col0 = bc * 128;

    const __half* __restrict__ Qh = g_QRh + (size_t)h * TT * NN;
    const __half* __restrict__ Ql = g_QRl + (size_t)h * TT * NN;

    const int tid = threadIdx.x;
    const int lane = tid & 31, wid = tid >> 5;
    const int wm = (wid >> 2) * 64, wn = (wid & 3) * 32;
    const int mi = lane >> 3, r8 = lane & 7;
    const int q = lane & 3, l4 = lane >> 2;

    auto load = [&](int stg, int k0) {
        const uint32_t sb = smb + (uint32_t)stg * G1_STAGE_H * 2;
#pragma unroll
        for (int it = 0; it < 6; it++) {
            int c = it * 256 + tid;
            int t = c >> 9;               // 0:Ah 1:Al 2:Bh
            int rr = (c & 511) >> 2;
            int kg = c & 3;
            const __half* src =
                (t == 0 ? Qh + (size_t)(row0 + rr) * NN
                 : t == 1 ? Ql + (size_t)(row0 + rr) * NN
                          : Qh + (size_t)(col0 + rr) * NN) + k0 + kg * 8;
            cpa16(sb + (uint32_t)(t * 5120 + rr * AP + kg * 8) * 2, src);
        }
        cp_commit();
    };

    float acc[4][4][4];
#pragma unroll
    for (int a = 0; a < 4; a++)
#pragma unroll
        for (int b = 0; b < 4; b++)
#pragma unroll
            for (int cc = 0; cc < 4; cc++) acc[a][b][cc] = 0.0f;

    const int NS = NN / 32;
    load(0, 0);
    load(1, 32);

    for (int s = 0; s < NS; s++) {
        if (s + 1 < NS) cp_wait<1>(); else cp_wait<0>();
        __syncthreads();
        const __half* st = sm + (size_t)(s % 3) * G1_STAGE_H;
        const __half* sAh = st;
        const __half* sAl = st + 5120;
        const __half* sBh = st + 10240;
#pragma unroll
        for (int kk = 0; kk < 32; kk += 16) {
            uint32_t fbh[4][2];
#pragma unroll
            for (int p = 0; p < 2; p++) {
                uint32_t r[4];
                ldsm4(r, smaddr(sBh + (size_t)(wn + p * 16 + (mi >> 1) * 8 + r8) * AP + kk + (mi & 1) * 8));
                fbh[p * 2][0] = r[0]; fbh[p * 2][1] = r[1];
                fbh[p * 2 + 1][0] = r[2]; fbh[p * 2 + 1][1] = r[3];
            }
#pragma unroll
            for (int mt = 0; mt < 4; mt++) {
                uint32_t fah[4], fal[4];
                ldsm4(fah, smaddr(sAh + (size_t)(wm + mt * 16 + (mi & 1) * 8 + r8) * AP + kk + (mi >> 1) * 8));
                ldsm4(fal, smaddr(sAl + (size_t)(wm + mt * 16 + (mi & 1) * 8 + r8) * AP + kk + (mi >> 1) * 8));
#pragma unroll
                for (int nt = 0; nt < 4; nt++) {
                    mmaf16(acc[mt][nt], fah, fbh[nt]);
                    mmaf16(acc[mt][nt], fal, fbh[nt]);
                }
            }
        }
        if (s + 2 < NS) load((s + 2) % 3, (s + 2) * 32);
    }

    const float scale = 1.0f / 64.0f;
    __half* Sh = g_Sh + (size_t)h * TT * TT;
    const bool mirror = (br != bc);

    // direct writes (fp16 only)
#pragma unroll
    for (int mt = 0; mt < 4; mt++)
#pragma unroll
        for (int nt = 0; nt < 4; nt++) {
            int c = col0 + wn + nt * 8 + q * 2;
#pragma unroll
            for (int hh = 0; hh < 2; hh++) {
                int r = row0 + wm + mt * 16 + l4 + hh * 8;
                __half h0 = __float2half_rn(acc[mt][nt][hh * 2 + 0] * scale);
                __half h1 = __float2half_rn(acc[mt][nt][hh * 2 + 1] * scale);
                *(__half2*)&Sh[(size_t)r * TT + c] = __halves2half2(h0, h1);
            }
        }

    // mirror writes via smem transpose
    if (mirror) {
        __syncthreads();
        __half* tsh = sm;
#pragma unroll
        for (int mt = 0; mt < 4; mt++)
#pragma unroll
            for (int nt = 0; nt < 4; nt++)
#pragma unroll
                for (int hh = 0; hh < 2; hh++) {
                    int rl = wm + mt * 16 + l4 + hh * 8;
                    int cl = wn + nt * 8 + q * 2;
                    tsh[(size_t)cl * TRPITCH + rl] =
                        __float2half_rn(acc[mt][nt][hh * 2 + 0] * scale);
                    tsh[(size_t)(cl + 1) * TRPITCH + rl] =
                        __float2half_rn(acc[mt][nt][hh * 2 + 1] * scale);
                }
        __syncthreads();
        int cr = tid >> 1, cb2 = (tid & 1) * 64;
        size_t base = (size_t)(col0 + cr) * TT + row0 + cb2;
#pragma unroll
        for (int j = 0; j < 8; j++)
            *(uint4*)&Sh[base + j * 8] = *(uint4*)&tsh[(size_t)cr * TRPITCH + cb2 + j * 8];
    }
}

// ---------------------------------------------------------------------------
// Kernel 4: O = S V  (single term Sh*Vh; 4-stage pipeline)
// stage: A[128][AP] (5120) + B[32][BPITCH] (4352) = 9472 halves
// ---------------------------------------------------------------------------
#define G2_STAGE_H 9472
#define G2_DSMEM (4 * G2_STAGE_H * 2)

__global__ __launch_bounds__(256, 2) void gemm2(float* __restrict__ O) {
    extern __shared__ __align__(16) __half sm[];
    const uint32_t smb = smaddr(sm);

    const int h = blockIdx.z;
    const int col0 = blockIdx.x * 128, row0 = blockIdx.y * 128;

    const __half* __restrict__ Sh = g_Sh + (size_t)h * TT * TT;
    const __half* __restrict__ Vh = g_Vh + (size_t)h * TT * NN;
    float* __restrict__ Oh = O + (size_t)h * TT * NN;

    const int tid = threadIdx.x;
    const int lane = tid & 31, wid = tid >> 5;
    const int wm = (wid >> 2) * 64, wn = (wid & 3) * 32;
    const int mi = lane >> 3, r8 = lane & 7;
    const int q = lane & 3, l4 = lane >> 2;

    auto load = [&](int stg, int k0) {
        const uint32_t sb = smb + (uint32_t)stg * G2_STAGE_H * 2;
#pragma unroll
        for (int it = 0; it < 4; it++) {
            int c = it * 256 + tid;       // 0..1023
            int t = c >> 9;               // 0:A 1:B
            int c2 = c & 511;
            if (t == 0) {
                int rr = c2 >> 2, kg = c2 & 3;
                cpa16(sb + (uint32_t)(rr * AP + kg * 8) * 2,
                      Sh + (size_t)(row0 + rr) * TT + k0 + kg * 8);
            } else {
                int rr = c2 >> 4, cg = c2 & 15;
                cpa16(sb + (uint32_t)(5120 + rr * BPITCH + cg * 8) * 2,
                      Vh + (size_t)(k0 + rr) * NN + col0 + cg * 8);
            }
        }
        cp_commit();
    };

    float acc[4][4][4];
#pragma unroll
    for (int a = 0; a < 4; a++)
#pragma unroll
        for (int b = 0; b < 4; b++)
#pragma unroll
            for (int cc = 0; cc < 4; cc++) acc[a][b][cc] = 0.0f;

    const int NS = TT / 32;
    load(0, 0);
    load(1, 32);
    load(2, 64);

    for (int s = 0; s < NS; s++) {
        if (s + 2 < NS) cp_wait<2>();
        else if (s + 1 < NS) cp_wait<1>();
        else cp_wait<0>();
        __syncthreads();
        const __half* st = sm + (size_t)(s & 3) * G2_STAGE_H;
        const __half* sA = st;
        const __half* sB = st + 5120;
#pragma unroll
        for (int kk = 0; kk < 32; kk += 16) {
            uint32_t fbh[4][2];
#pragma unroll
            for (int p = 0; p < 2; p++) {
                uint32_t r[4];
                ldsm4t(r, smaddr(sB + (size_t)(kk + (mi & 1) * 8 + r8) * BPITCH + wn + p * 16 + (mi >> 1) * 8));
                fbh[p * 2][0] = r[0]; fbh[p * 2][1] = r[1];
                fbh[p * 2 + 1][0] = r[2]; fbh[p * 2 + 1][1] = r[3];
            }
#pragma unroll
            for (int mt = 0; mt < 4; mt++) {
                uint32_t fah[4];
                ldsm4(fah, smaddr(sA + (size_t)(wm + mt * 16 + (mi & 1) * 8 + r8) * AP + kk + (mi >> 1) * 8));
#pragma unroll
                for (int nt = 0; nt < 4; nt++)
                    mmaf16(acc[mt][nt], fah, fbh[nt]);
            }
        }
        if (s + 3 < NS) load((s + 3) & 3, (s + 3) * 32);
    }

#pragma unroll
    for (int mt = 0; mt < 4; mt++)
#pragma unroll
        for (int nt = 0; nt < 4; nt++) {
            int c = col0 + wn + nt * 8 + q * 2;
#pragma unroll
            for (int hh = 0; hh < 2; hh++) {
                int r = row0 + wm + mt * 16 + l4 + hh * 8;
                *(float2*)&Oh[(size_t)r * NN + c] =
                    make_float2(acc[mt][nt][hh * 2 + 0], acc[mt][nt][hh * 2 + 1]);
            }
        }
}

// ---------------------------------------------------------------------------
// Launch
// ---------------------------------------------------------------------------
extern "C" void kernel_launch(void* const* d_in, const int* in_sizes, int n_in,
                              void* d_out, int out_size) {
    const float* Q = (const float*)d_in[0];
    const float* V = (const float*)d_in[2];
    float* O = (float*)d_out;

    cudaFuncSetAttribute(gemm1, cudaFuncAttributeMaxDynamicSharedMemorySize, G1_DSMEM);
    cudaFuncSetAttribute(gemm2, cudaFuncAttributeMaxDynamicSharedMemorySize, G2_DSMEM);

    {   // RoPE + fp16 split
        int threads = 256;
        int blocks = (int)(((size_t)NHT * TT * NN / 2) / threads);
        rope_split<<<blocks, threads>>>(Q);
    }
    {   // V -> fp16
        int threads = 256;
        int blocks = (int)(((size_t)NHT * TT * NN / 8) / threads);
        v_half<<<blocks, threads>>>(V);
    }
    {   // S = scale * QR QR^T (136 upper-tri tiles per head)
        dim3 grid(136, NHT);
        gemm1<<<grid, 256, G1_DSMEM>>>();
    }
    {   // O = S V
        dim3 grid(NN / 128, TT / 128, NHT);
        gemm2<<<grid, 256, G2_DSMEM>>>(O);
    }
}